// round 1
// baseline (speedup 1.0000x reference)
#include <cuda_runtime.h>
#include <math.h>

#define NB 128      // batch
#define NTT 32      // timesteps
#define NV 32000    // vocab
#define NE 128      // embed dim
#define NH 256      // hidden
#define NF 2048     // feature dim
#define NG 1024     // 4*H (gates)
#define LDW (NE + NF)   // W_ih row stride = 2176

// ---------------- scratch (device globals; no allocation allowed) ------------
__device__ float g_embed[NTT * NB * NE];       // [t][b][e]    2 MB
__device__ float g_gates_emb[NTT * NB * NG];   // [t][b][j]   16 MB
__device__ float g_gates_base[NB * NG];        // [b][j]
__device__ float g_gates[NB * NG];             // per-step gates
__device__ float g_h[NB * NH];
__device__ float g_c[NB * NH];
__device__ float g_Hall[NTT * NB * NH];        // [t][b][h]    4 MB

// ---------------- gather: g_embed[(t*NB+b)*NE + e] = embeddings[captions[b,t]] ----
__global__ void gather_embed_kernel(const int* __restrict__ captions,
                                    const float* __restrict__ embeddings) {
    int idx = blockIdx.x * blockDim.x + threadIdx.x;
    if (idx >= NTT * NB * NE) return;
    int e = idx % NE;
    int m = idx / NE;          // t*NB + b
    int t = m / NB;
    int b = m % NB;
    int tok = captions[b * NTT + t];
    g_embed[idx] = embeddings[tok * NE + e];
}

// ---------------- h0/c0 init: (128,2048)@(2048,256) twice -------------------
__global__ void init_hc_kernel(const float* __restrict__ features,
                               const float* __restrict__ WH, const float* __restrict__ bH,
                               const float* __restrict__ WC, const float* __restrict__ bC) {
    __shared__ float fs[NF];
    int b = blockIdx.x;
    for (int i = threadIdx.x; i < NF; i += blockDim.x)
        fs[i] = features[b * NF + i];
    __syncthreads();
    int h = threadIdx.x;   // 256 threads
    float accH = bH[h];
    float accC = bC[h];
    #pragma unroll 4
    for (int f = 0; f < NF; f++) {
        float fv = fs[f];
        accH = fmaf(fv, WH[f * NH + h], accH);
        accC = fmaf(fv, WC[f * NH + h], accC);
    }
    g_h[b * NH + h] = accH;
    g_c[b * NH + h] = accC;
}

// ---------------- generic NT sgemm: C[M,N] = A(M,K) @ B(N,K)^T (+adds +biases) ----
// BM=BN=64, BK=16, 256 threads, 4x4 per thread. All dims divisible (checked).
__global__ void sgemm_nt64(const float* __restrict__ A, int lda,
                           const float* __restrict__ B, int ldb,
                           float* __restrict__ C, int ldc, int K,
                           const float* __restrict__ add1,
                           const float* __restrict__ add2,
                           const float* __restrict__ bias1,
                           const float* __restrict__ bias2) {
    __shared__ float As[16][64];
    __shared__ float Bs[16][64];
    int m0 = blockIdx.y * 64;
    int n0 = blockIdx.x * 64;
    int tid = threadIdx.x;
    int lm = tid >> 2;            // 0..63 (row within tile)
    int lk = (tid & 3) * 4;       // 0,4,8,12
    int tx = tid & 15;
    int ty = tid >> 4;
    float acc[4][4] = {};

    for (int k0 = 0; k0 < K; k0 += 16) {
        float4 av = *(const float4*)&A[(size_t)(m0 + lm) * lda + k0 + lk];
        float4 bv = *(const float4*)&B[(size_t)(n0 + lm) * ldb + k0 + lk];
        As[lk + 0][lm] = av.x; As[lk + 1][lm] = av.y;
        As[lk + 2][lm] = av.z; As[lk + 3][lm] = av.w;
        Bs[lk + 0][lm] = bv.x; Bs[lk + 1][lm] = bv.y;
        Bs[lk + 2][lm] = bv.z; Bs[lk + 3][lm] = bv.w;
        __syncthreads();
        #pragma unroll
        for (int kk = 0; kk < 16; kk++) {
            float4 a = *(const float4*)&As[kk][ty * 4];
            float4 b = *(const float4*)&Bs[kk][tx * 4];
            float ar[4] = {a.x, a.y, a.z, a.w};
            float br[4] = {b.x, b.y, b.z, b.w};
            #pragma unroll
            for (int i = 0; i < 4; i++)
                #pragma unroll
                for (int j = 0; j < 4; j++)
                    acc[i][j] = fmaf(ar[i], br[j], acc[i][j]);
        }
        __syncthreads();
    }

    #pragma unroll
    for (int i = 0; i < 4; i++) {
        int m = m0 + ty * 4 + i;
        #pragma unroll
        for (int j = 0; j < 4; j++) {
            int n = n0 + tx * 4 + j;
            float v = acc[i][j];
            if (add1)  v += add1[(size_t)m * ldc + n];
            if (add2)  v += add2[(size_t)m * ldc + n];
            if (bias1) v += bias1[n];
            if (bias2) v += bias2[n];
            C[(size_t)m * ldc + n] = v;
        }
    }
}

// ---------------- LSTM elementwise cell -------------------------------------
__global__ void lstm_cell_kernel(int t) {
    int idx = blockIdx.x * blockDim.x + threadIdx.x;   // 128*256
    int b = idx >> 8;
    int h = idx & 255;
    const float* g = g_gates + b * NG;
    float xi = g[h];
    float xf = g[256 + h];
    float xg = g[512 + h];
    float xo = g[768 + h];
    float i_ = 1.f / (1.f + expf(-xi));
    float f_ = 1.f / (1.f + expf(-xf));
    float gg = tanhf(xg);
    float o_ = 1.f / (1.f + expf(-xo));
    float c = f_ * g_c[idx] + i_ * gg;
    float hn = o_ * tanhf(c);
    g_c[idx] = c;
    g_h[idx] = hn;
    g_Hall[t * NB * NH + idx] = hn;
}

// ---------------- fc: out[b][t][v] = Hall[t][b][:] @ fc_W + fc_b ------------
// NN sgemm M=4096 (t,b), N=32000, K=256. 128x128 tile, BK=8, 256 thr, 8x8/thr.
__global__ void sgemm_nn_fc(const float* __restrict__ A,   // g_Hall, lda=256
                            const float* __restrict__ Bw,  // fc_W (256, 32000)
                            const float* __restrict__ bias,
                            float* __restrict__ out) {
    __shared__ float As[8][128];
    __shared__ float Bs[8][128];
    int m0 = blockIdx.y * 128;
    int n0 = blockIdx.x * 128;
    int tid = threadIdx.x;
    int am = tid >> 1;            // 0..127
    int ak = (tid & 1) * 4;       // 0,4
    int br = tid >> 5;            // 0..7
    int bn = (tid & 31) * 4;      // 0..124
    int tx = tid & 15;
    int ty = tid >> 4;
    float acc[8][8] = {};

    for (int k0 = 0; k0 < NH; k0 += 8) {
        float4 av = *(const float4*)&A[(size_t)(m0 + am) * NH + k0 + ak];
        float4 bv = *(const float4*)&Bw[(size_t)(k0 + br) * NV + n0 + bn];
        As[ak + 0][am] = av.x; As[ak + 1][am] = av.y;
        As[ak + 2][am] = av.z; As[ak + 3][am] = av.w;
        *(float4*)&Bs[br][bn] = bv;
        __syncthreads();
        #pragma unroll
        for (int kk = 0; kk < 8; kk++) {
            float4 a0 = *(const float4*)&As[kk][ty * 8];
            float4 a1 = *(const float4*)&As[kk][ty * 8 + 4];
            float4 b0 = *(const float4*)&Bs[kk][tx * 8];
            float4 b1 = *(const float4*)&Bs[kk][tx * 8 + 4];
            float ar[8] = {a0.x, a0.y, a0.z, a0.w, a1.x, a1.y, a1.z, a1.w};
            float brr[8] = {b0.x, b0.y, b0.z, b0.w, b1.x, b1.y, b1.z, b1.w};
            #pragma unroll
            for (int i = 0; i < 8; i++)
                #pragma unroll
                for (int j = 0; j < 8; j++)
                    acc[i][j] = fmaf(ar[i], brr[j], acc[i][j]);
        }
        __syncthreads();
    }

    // epilogue: row m = t*128 + b  ->  out row (b*NTT + t)
    #pragma unroll
    for (int i = 0; i < 8; i++) {
        int m = m0 + ty * 8 + i;
        int t = m >> 7;
        int b = m & 127;
        float* orow = out + (size_t)(b * NTT + t) * NV;
        int n = n0 + tx * 8;
        float4 v0, v1;
        v0.x = acc[i][0] + bias[n + 0]; v0.y = acc[i][1] + bias[n + 1];
        v0.z = acc[i][2] + bias[n + 2]; v0.w = acc[i][3] + bias[n + 3];
        v1.x = acc[i][4] + bias[n + 4]; v1.y = acc[i][5] + bias[n + 5];
        v1.z = acc[i][6] + bias[n + 6]; v1.w = acc[i][7] + bias[n + 7];
        *(float4*)&orow[n] = v0;
        *(float4*)&orow[n + 4] = v1;
    }
}

// ---------------- launch ----------------------------------------------------
extern "C" void kernel_launch(void* const* d_in, const int* in_sizes, int n_in,
                              void* d_out, int out_size) {
    const float* features   = (const float*)d_in[0];
    const int*   captions   = (const int*)d_in[1];
    const float* embeddings = (const float*)d_in[2];
    const float* W_ih       = (const float*)d_in[3];
    const float* b_ih       = (const float*)d_in[4];
    const float* W_hh       = (const float*)d_in[5];
    const float* b_hh       = (const float*)d_in[6];
    const float* fc_W       = (const float*)d_in[7];
    const float* fc_b       = (const float*)d_in[8];
    // d_in[9..14] = attention weights: provably unused (softmax over length-1 axis == 1)
    const float* initH_W    = (const float*)d_in[15];
    const float* initH_b    = (const float*)d_in[16];
    const float* initC_W    = (const float*)d_in[17];
    const float* initC_b    = (const float*)d_in[18];
    float* out = (float*)d_out;

    void *p_embed_, *p_gemb_, *p_gbase_, *p_gates_, *p_h_, *p_Hall_;
    cudaGetSymbolAddress(&p_embed_, g_embed);
    cudaGetSymbolAddress(&p_gemb_,  g_gates_emb);
    cudaGetSymbolAddress(&p_gbase_, g_gates_base);
    cudaGetSymbolAddress(&p_gates_, g_gates);
    cudaGetSymbolAddress(&p_h_,     g_h);
    cudaGetSymbolAddress(&p_Hall_,  g_Hall);
    float* p_embed = (float*)p_embed_;
    float* p_gemb  = (float*)p_gemb_;
    float* p_gbase = (float*)p_gbase_;
    float* p_gates = (float*)p_gates_;
    float* p_h     = (float*)p_h_;
    float* p_Hall  = (float*)p_Hall_;

    // 1) gather word embeddings
    gather_embed_kernel<<<(NTT * NB * NE + 255) / 256, 256>>>(captions, embeddings);

    // 2) gates_emb[t,b,:] = embed @ W_ih[:, :E]^T   (M=4096, N=1024, K=128)
    sgemm_nt64<<<dim3(NG / 64, (NTT * NB) / 64), 256>>>(
        p_embed, NE, W_ih, LDW, p_gemb, NG, NE,
        nullptr, nullptr, nullptr, nullptr);

    // 3) gates_base = features @ W_ih[:, E:]^T + b_ih + b_hh  (M=128, N=1024, K=2048)
    sgemm_nt64<<<dim3(NG / 64, NB / 64), 256>>>(
        features, NF, W_ih + NE, LDW, p_gbase, NG, NF,
        nullptr, nullptr, b_ih, b_hh);

    // 4) h0, c0
    init_hc_kernel<<<NB, NH>>>(features, initH_W, initH_b, initC_W, initC_b);

    // 5) sequential LSTM steps
    for (int t = 0; t < NTT; t++) {
        sgemm_nt64<<<dim3(NG / 64, NB / 64), 256>>>(
            p_h, NH, W_hh, NH, p_gates, NG, NH,
            p_gbase, p_gemb + (size_t)t * NB * NG, nullptr, nullptr);
        lstm_cell_kernel<<<NB, NH>>>(t);
    }

    // 6) fc projection: one big GEMM (4096, 256) @ (256, 32000)
    sgemm_nn_fc<<<dim3(NV / 128, (NTT * NB) / 128), 256>>>(p_Hall, fc_W, fc_b, out);
}

// round 4
// speedup vs baseline: 1.7711x; 1.7711x over previous
#include <cuda_runtime.h>
#include <stdint.h>
#include <math.h>

#define NB 128      // batch
#define NTT 32      // timesteps
#define NV 32000    // vocab
#define NE 128      // embed dim
#define NH 256      // hidden
#define NF 2048     // feature dim
#define NG 1024     // 4*H (gates)
#define LDW (NE + NF)   // W_ih row stride = 2176

// ---------------- scratch (device globals; no allocation allowed) ------------
__device__ float g_embed[NTT * NB * NE];       // [t][b][e]
__device__ float g_gates_emb[NTT * NB * NG];   // [t][b][j]
__device__ float g_gates_base[NB * NG];        // [b][j]
__device__ float g_gates[NB * NG];             // per-step gates
__device__ float g_h[NB * NH];
__device__ float g_c[NB * NH];
__device__ float g_Hall[NTT * NB * NH];        // [t][b][h]
__device__ float g_initpart[2 * 8 * NB * NH];  // K-split partials for h0/c0

// ---------------- helpers ----------------------------------------------------
__device__ __forceinline__ uint32_t f2tf32(float x) {
    uint32_t u;
    asm("cvt.rna.tf32.f32 %0, %1;" : "=r"(u) : "f"(x));
    return u;
}

__device__ __forceinline__ void mma_tf32(float* d, const uint32_t* a, const uint32_t* b) {
    asm volatile(
        "mma.sync.aligned.m16n8k8.row.col.f32.tf32.tf32.f32 "
        "{%0,%1,%2,%3}, {%4,%5,%6,%7}, {%8,%9}, {%0,%1,%2,%3};"
        : "+f"(d[0]), "+f"(d[1]), "+f"(d[2]), "+f"(d[3])
        : "r"(a[0]), "r"(a[1]), "r"(a[2]), "r"(a[3]), "r"(b[0]), "r"(b[1]));
}

// ---------------- gather: g_embed[(t*NB+b)*NE + e] = embeddings[captions[b,t]] ----
__global__ void gather_embed_kernel(const int* __restrict__ captions,
                                    const float* __restrict__ embeddings) {
    int idx = blockIdx.x * blockDim.x + threadIdx.x;
    if (idx >= NTT * NB * NE) return;
    int e = idx % NE;
    int m = idx / NE;          // t*NB + b
    int t = m / NB;
    int b = m % NB;
    int tok = captions[b * NTT + t];
    g_embed[idx] = embeddings[tok * NE + e];
}

// ---------------- init h0/c0: NN gemm with deterministic K-split -------------
__global__ void init_part_kernel(const float* __restrict__ A,   // features (NB, NF)
                                 const float* __restrict__ W,   // (NF, NH)
                                 int mat) {
    __shared__ float As[16][64];
    __shared__ float Bs[16][64];
    int n0 = blockIdx.x * 64;
    int m0 = blockIdx.y * 64;
    int kz = blockIdx.z;
    int tid = threadIdx.x;
    int lm = tid >> 2, lk = (tid & 3) * 4;
    int kr = tid >> 4, n4 = (tid & 15) * 4;
    int tx = tid & 15, ty = tid >> 4;
    float acc[4][4] = {};

    for (int k0 = kz * 256; k0 < kz * 256 + 256; k0 += 16) {
        float4 av = *(const float4*)&A[(size_t)(m0 + lm) * NF + k0 + lk];
        As[lk + 0][lm] = av.x; As[lk + 1][lm] = av.y;
        As[lk + 2][lm] = av.z; As[lk + 3][lm] = av.w;
        float4 bv = *(const float4*)&W[(size_t)(k0 + kr) * NH + n0 + n4];
        *(float4*)&Bs[kr][n4] = bv;
        __syncthreads();
        #pragma unroll
        for (int kk = 0; kk < 16; kk++) {
            float4 a = *(const float4*)&As[kk][ty * 4];
            float4 b = *(const float4*)&Bs[kk][tx * 4];
            float ar[4] = {a.x, a.y, a.z, a.w};
            float br[4] = {b.x, b.y, b.z, b.w};
            #pragma unroll
            for (int i = 0; i < 4; i++)
                #pragma unroll
                for (int j = 0; j < 4; j++)
                    acc[i][j] = fmaf(ar[i], br[j], acc[i][j]);
        }
        __syncthreads();
    }
    float* dst = g_initpart + ((size_t)(mat * 8 + kz) * NB) * NH;
    #pragma unroll
    for (int i = 0; i < 4; i++)
        #pragma unroll
        for (int j = 0; j < 4; j++)
            dst[(size_t)(m0 + ty * 4 + i) * NH + n0 + tx * 4 + j] = acc[i][j];
}

__global__ void init_reduce_kernel(const float* __restrict__ bH,
                                   const float* __restrict__ bC) {
    int idx = blockIdx.x * blockDim.x + threadIdx.x;   // NB*NH
    int h = idx & 255;
    float sH = bH[h], sC = bC[h];
    #pragma unroll
    for (int z = 0; z < 8; z++) {
        sH += g_initpart[(size_t)z * NB * NH + idx];
        sC += g_initpart[(size_t)(8 + z) * NB * NH + idx];
    }
    g_h[idx] = sH;
    g_c[idx] = sC;
}

// ---------------- generic NT sgemm: C[M,N] = A(M,K) @ B(N,K)^T (+adds +biases) ----
__global__ void sgemm_nt64(const float* __restrict__ A, int lda,
                           const float* __restrict__ B, int ldb,
                           float* __restrict__ C, int ldc, int K,
                           const float* __restrict__ add1,
                           const float* __restrict__ add2,
                           const float* __restrict__ bias1,
                           const float* __restrict__ bias2) {
    __shared__ float As[16][64];
    __shared__ float Bs[16][64];
    int m0 = blockIdx.y * 64;
    int n0 = blockIdx.x * 64;
    int tid = threadIdx.x;
    int lm = tid >> 2;
    int lk = (tid & 3) * 4;
    int tx = tid & 15;
    int ty = tid >> 4;
    float acc[4][4] = {};

    for (int k0 = 0; k0 < K; k0 += 16) {
        float4 av = *(const float4*)&A[(size_t)(m0 + lm) * lda + k0 + lk];
        float4 bv = *(const float4*)&B[(size_t)(n0 + lm) * ldb + k0 + lk];
        As[lk + 0][lm] = av.x; As[lk + 1][lm] = av.y;
        As[lk + 2][lm] = av.z; As[lk + 3][lm] = av.w;
        Bs[lk + 0][lm] = bv.x; Bs[lk + 1][lm] = bv.y;
        Bs[lk + 2][lm] = bv.z; Bs[lk + 3][lm] = bv.w;
        __syncthreads();
        #pragma unroll
        for (int kk = 0; kk < 16; kk++) {
            float4 a = *(const float4*)&As[kk][ty * 4];
            float4 b = *(const float4*)&Bs[kk][tx * 4];
            float ar[4] = {a.x, a.y, a.z, a.w};
            float br[4] = {b.x, b.y, b.z, b.w};
            #pragma unroll
            for (int i = 0; i < 4; i++)
                #pragma unroll
                for (int j = 0; j < 4; j++)
                    acc[i][j] = fmaf(ar[i], br[j], acc[i][j]);
        }
        __syncthreads();
    }

    #pragma unroll
    for (int i = 0; i < 4; i++) {
        int m = m0 + ty * 4 + i;
        #pragma unroll
        for (int j = 0; j < 4; j++) {
            int n = n0 + tx * 4 + j;
            float v = acc[i][j];
            if (add1)  v += add1[(size_t)m * ldc + n];
            if (add2)  v += add2[(size_t)m * ldc + n];
            if (bias1) v += bias1[n];
            if (bias2) v += bias2[n];
            C[(size_t)m * ldc + n] = v;
        }
    }
}

// ---------------- LSTM elementwise cell -------------------------------------
__global__ void lstm_cell_kernel(int t) {
    int idx = blockIdx.x * blockDim.x + threadIdx.x;   // 128*256
    int b = idx >> 8;
    int h = idx & 255;
    const float* g = g_gates + b * NG;
    float xi = g[h];
    float xf = g[256 + h];
    float xg = g[512 + h];
    float xo = g[768 + h];
    float i_ = 1.f / (1.f + expf(-xi));
    float f_ = 1.f / (1.f + expf(-xf));
    float gg = tanhf(xg);
    float o_ = 1.f / (1.f + expf(-xo));
    float c = f_ * g_c[idx] + i_ * gg;
    float hn = o_ * tanhf(c);
    g_c[idx] = c;
    g_h[idx] = hn;
    g_Hall[t * NB * NH + idx] = hn;
}

// ---------------- fc: tf32 tensor-core GEMM ---------------------------------
// out[(b*T+t)][v] = Hall[(t*B+b)][:] @ fc_W + fc_b
// M=4096, N=32000, K=256. BM=BN=128, BK=16, 256 thr (8 warps, 2x4),
// warp tile 64x32 via m16n8k8 (4x4 mma tiles), double-buffered smem.
__global__ void __launch_bounds__(256) fc_tf32_kernel(const float* __restrict__ A,
                                                      const float* __restrict__ Bw,
                                                      const float* __restrict__ bias,
                                                      float* __restrict__ out) {
    __shared__ uint32_t As[2][128 * 20];   // [m][k] pad 16->20
    __shared__ uint32_t Bs[2][16 * 132];   // [k][n] pad 128->132
    const int tid = threadIdx.x;
    const int m0 = blockIdx.y * 128, n0 = blockIdx.x * 128;
    const int lane = tid & 31, warp = tid >> 5;
    const int wm = (warp >> 2) * 64, wn = (warp & 3) * 32;
    const int g = lane >> 2, tig = lane & 3;
    const int a_row = tid >> 2, a_col = (tid & 3) * 4;   // 64 rows/pass, 2 passes
    const int b_row = tid >> 5, b_col = (tid & 31) * 4;  // 8 rows/pass, 2 passes
    const float* Ag = A + (size_t)(m0 + a_row) * NH + a_col;
    const float* Bg = Bw + (size_t)b_row * NV + n0 + b_col;

    float acc[4][4][4];
    #pragma unroll
    for (int i = 0; i < 4; i++)
        #pragma unroll
        for (int j = 0; j < 4; j++)
            #pragma unroll
            for (int r = 0; r < 4; r++) acc[i][j][r] = 0.f;

    float4 pa[2], pb[2];
    // prologue: tile k0 = 0
    pa[0] = *(const float4*)(Ag);
    pa[1] = *(const float4*)(Ag + (size_t)64 * NH);
    pb[0] = *(const float4*)(Bg);
    pb[1] = *(const float4*)(Bg + (size_t)8 * NV);
    {
        uint32_t* d0 = &As[0][a_row * 20 + a_col];
        d0[0] = f2tf32(pa[0].x); d0[1] = f2tf32(pa[0].y);
        d0[2] = f2tf32(pa[0].z); d0[3] = f2tf32(pa[0].w);
        uint32_t* d1 = &As[0][(a_row + 64) * 20 + a_col];
        d1[0] = f2tf32(pa[1].x); d1[1] = f2tf32(pa[1].y);
        d1[2] = f2tf32(pa[1].z); d1[3] = f2tf32(pa[1].w);
        uint32_t* e0 = &Bs[0][b_row * 132 + b_col];
        e0[0] = f2tf32(pb[0].x); e0[1] = f2tf32(pb[0].y);
        e0[2] = f2tf32(pb[0].z); e0[3] = f2tf32(pb[0].w);
        uint32_t* e1 = &Bs[0][(b_row + 8) * 132 + b_col];
        e1[0] = f2tf32(pb[1].x); e1[1] = f2tf32(pb[1].y);
        e1[2] = f2tf32(pb[1].z); e1[3] = f2tf32(pb[1].w);
    }
    __syncthreads();

    #pragma unroll 1
    for (int it = 0; it < 16; it++) {
        const int cur = it & 1;
        if (it < 15) {
            const int k0 = (it + 1) * 16;
            pa[0] = *(const float4*)(Ag + k0);
            pa[1] = *(const float4*)(Ag + (size_t)64 * NH + k0);
            pb[0] = *(const float4*)(Bg + (size_t)k0 * NV);
            pb[1] = *(const float4*)(Bg + (size_t)(k0 + 8) * NV);
        }
        #pragma unroll
        for (int kk = 0; kk < 2; kk++) {
            uint32_t af[4][4], bf[4][2];
            #pragma unroll
            for (int ti = 0; ti < 4; ti++) {
                int r = wm + ti * 16 + g;
                af[ti][0] = As[cur][r * 20 + kk * 8 + tig];
                af[ti][1] = As[cur][(r + 8) * 20 + kk * 8 + tig];
                af[ti][2] = As[cur][r * 20 + kk * 8 + tig + 4];
                af[ti][3] = As[cur][(r + 8) * 20 + kk * 8 + tig + 4];
            }
            #pragma unroll
            for (int tj = 0; tj < 4; tj++) {
                int cb = wn + tj * 8 + g;
                bf[tj][0] = Bs[cur][(kk * 8 + tig) * 132 + cb];
                bf[tj][1] = Bs[cur][(kk * 8 + tig + 4) * 132 + cb];
            }
            #pragma unroll
            for (int ti = 0; ti < 4; ti++)
                #pragma unroll
                for (int tj = 0; tj < 4; tj++)
                    mma_tf32(acc[ti][tj], af[ti], bf[tj]);
        }
        if (it < 15) {
            const int nb = cur ^ 1;
            uint32_t* d0 = &As[nb][a_row * 20 + a_col];
            d0[0] = f2tf32(pa[0].x); d0[1] = f2tf32(pa[0].y);
            d0[2] = f2tf32(pa[0].z); d0[3] = f2tf32(pa[0].w);
            uint32_t* d1 = &As[nb][(a_row + 64) * 20 + a_col];
            d1[0] = f2tf32(pa[1].x); d1[1] = f2tf32(pa[1].y);
            d1[2] = f2tf32(pa[1].z); d1[3] = f2tf32(pa[1].w);
            uint32_t* e0 = &Bs[nb][b_row * 132 + b_col];
            e0[0] = f2tf32(pb[0].x); e0[1] = f2tf32(pb[0].y);
            e0[2] = f2tf32(pb[0].z); e0[3] = f2tf32(pb[0].w);
            uint32_t* e1 = &Bs[nb][(b_row + 8) * 132 + b_col];
            e1[0] = f2tf32(pb[1].x); e1[1] = f2tf32(pb[1].y);
            e1[2] = f2tf32(pb[1].z); e1[3] = f2tf32(pb[1].w);
        }
        __syncthreads();
    }

    // epilogue: row m = t*128 + b  ->  out row (b*NTT + t)
    #pragma unroll
    for (int ti = 0; ti < 4; ti++) {
        int mA = m0 + wm + ti * 16 + g;
        int mB = mA + 8;
        int tA = mA >> 7, bA = mA & 127;
        int tB = mB >> 7, bB = mB & 127;
        float* oA = out + (size_t)(bA * NTT + tA) * NV;
        float* oB = out + (size_t)(bB * NTT + tB) * NV;
        #pragma unroll
        for (int tj = 0; tj < 4; tj++) {
            int n = n0 + wn + tj * 8 + 2 * tig;
            float b0 = bias[n], b1 = bias[n + 1];
            float2 vA, vB;
            vA.x = acc[ti][tj][0] + b0; vA.y = acc[ti][tj][1] + b1;
            vB.x = acc[ti][tj][2] + b0; vB.y = acc[ti][tj][3] + b1;
            *(float2*)&oA[n] = vA;
            *(float2*)&oB[n] = vB;
        }
    }
}

// ---------------- launch ----------------------------------------------------
extern "C" void kernel_launch(void* const* d_in, const int* in_sizes, int n_in,
                              void* d_out, int out_size) {
    const float* features   = (const float*)d_in[0];
    const int*   captions   = (const int*)d_in[1];
    const float* embeddings = (const float*)d_in[2];
    const float* W_ih       = (const float*)d_in[3];
    const float* b_ih       = (const float*)d_in[4];
    const float* W_hh       = (const float*)d_in[5];
    const float* b_hh       = (const float*)d_in[6];
    const float* fc_W       = (const float*)d_in[7];
    const float* fc_b       = (const float*)d_in[8];
    // d_in[9..14] = attention weights: provably unused (softmax over length-1 axis == 1)
    const float* initH_W    = (const float*)d_in[15];
    const float* initH_b    = (const float*)d_in[16];
    const float* initC_W    = (const float*)d_in[17];
    const float* initC_b    = (const float*)d_in[18];
    float* out = (float*)d_out;

    void *p_embed_, *p_gemb_, *p_gbase_, *p_gates_, *p_h_, *p_Hall_;
    cudaGetSymbolAddress(&p_embed_, g_embed);
    cudaGetSymbolAddress(&p_gemb_,  g_gates_emb);
    cudaGetSymbolAddress(&p_gbase_, g_gates_base);
    cudaGetSymbolAddress(&p_gates_, g_gates);
    cudaGetSymbolAddress(&p_h_,     g_h);
    cudaGetSymbolAddress(&p_Hall_,  g_Hall);
    float* p_embed = (float*)p_embed_;
    float* p_gemb  = (float*)p_gemb_;
    float* p_gbase = (float*)p_gbase_;
    float* p_gates = (float*)p_gates_;
    float* p_h     = (float*)p_h_;
    float* p_Hall  = (float*)p_Hall_;

    // 1) gather word embeddings
    gather_embed_kernel<<<(NTT * NB * NE + 255) / 256, 256>>>(captions, embeddings);

    // 2) gates_emb[t,b,:] = embed @ W_ih[:, :E]^T   (M=4096, N=1024, K=128)
    sgemm_nt64<<<dim3(NG / 64, (NTT * NB) / 64), 256>>>(
        p_embed, NE, W_ih, LDW, p_gemb, NG, NE,
        nullptr, nullptr, nullptr, nullptr);

    // 3) gates_base = features @ W_ih[:, E:]^T + b_ih + b_hh  (M=128, N=1024, K=2048)
    sgemm_nt64<<<dim3(NG / 64, NB / 64), 256>>>(
        features, NF, W_ih + NE, LDW, p_gbase, NG, NF,
        nullptr, nullptr, b_ih, b_hh);

    // 4) h0, c0 via K-split GEMM + deterministic reduce
    init_part_kernel<<<dim3(NH / 64, NB / 64, 8), 256>>>(features, initH_W, 0);
    init_part_kernel<<<dim3(NH / 64, NB / 64, 8), 256>>>(features, initC_W, 1);
    init_reduce_kernel<<<NB, NH>>>(initH_b, initC_b);

    // 5) sequential LSTM steps
    for (int t = 0; t < NTT; t++) {
        sgemm_nt64<<<dim3(NG / 64, NB / 64), 256>>>(
            p_h, NH, W_hh, NH, p_gates, NG, NH,
            p_gbase, p_gemb + (size_t)t * NB * NG, nullptr, nullptr);
        lstm_cell_kernel<<<NB, NH>>>(t);
    }

    // 6) fc projection: tf32 tensor-core GEMM (4096, 256) @ (256, 32000)
    fc_tf32_kernel<<<dim3(NV / 128, (NTT * NB) / 128), 256>>>(p_Hall, fc_W, fc_b, out);
}